// round 12
// baseline (speedup 1.0000x reference)
#include <cuda_runtime.h>
#include <cuda_bf16.h>
#include <cstdint>

#define HIDDEN 64
#define BT 256          // 8 warps
#define SPW 8           // samples gathered per warp (8 warps x 8 = 64)
#define BEPS 2e-4f

// padded OR-dilated table: row (zi,yi) = (z0+64,y0+64), 8 words; bit = x0+64.
__device__ unsigned g_tab[65536 * 8];
__device__ unsigned g_mask[65536];      // base packed mask (exact fixup)

// ---------------- pack + dilate (289 blocks, 17x17 halo tiles) ----------------
__global__ __launch_bounds__(352) void pack_dilate_kernel(const float* __restrict__ vol) {
    __shared__ unsigned sp[81 * 4];   // 9x9 halo packed rows

    const int blk = blockIdx.x;
    const int a = blk / 17, b = blk % 17;
    const int t = threadIdx.x;

    if (t < 324) {
        const int w = t & 3, r = t >> 2;
        const int lz = r / 9, ly = r % 9;
        const int vz = 8 * a - 1 + lz, vy = 8 * b - 1 + ly;
        unsigned acc = 0u;
        if ((unsigned)vz < 128u && (unsigned)vy < 128u) {
            const float4* src = (const float4*)(vol + (((vz << 7) + vy) << 7)) + (w << 3);
            #pragma unroll
            for (int q = 0; q < 8; q++) {
                float4 v = __ldg(&src[q]);
                acc |= ((unsigned)(v.x != 0.0f)
                      | ((unsigned)(v.y != 0.0f) << 1)
                      | ((unsigned)(v.z != 0.0f) << 2)
                      | ((unsigned)(v.w != 0.0f) << 3)) << (q * 4);
            }
        }
        sp[t] = acc;
    }
    __syncthreads();

    if (t < 256 && a < 16 && b < 16) {
        const int r = t >> 2, w = t & 3;
        const int lz = (r >> 3) + 1, ly = (r & 7) + 1;
        const int vz = 8 * a + (r >> 3), vy = 8 * b + (r & 7);
        g_mask[(((vz << 7) + vy) << 2) + w] = sp[(lz * 9 + ly) * 4 + w];
    }

    if (t < 128) {
        const int r = t >> 1, half = t & 1;
        const int lz = r >> 3, ly = r & 7;
        const int z0 = 8 * a - 1 + lz, y0 = 8 * b - 1 + ly;
        if (z0 <= 127 && y0 <= 127) {
            const unsigned* p00 = sp + (lz * 9 + ly) * 4;
            const unsigned A0 = p00[0] | p00[4] | p00[36] | p00[40];
            const unsigned A1 = p00[1] | p00[5] | p00[37] | p00[41];
            const unsigned A2 = p00[2] | p00[6] | p00[38] | p00[42];
            const unsigned A3 = p00[3] | p00[7] | p00[39] | p00[43];
            const unsigned zi = (unsigned)(z0 + 64), yi = (unsigned)(y0 + 64);
            uint4* drow = ((uint4*)g_tab) + (((zi << 8) | yi) << 1);
            if (half == 0)
                drow[0] = make_uint4(0u, A0 << 31,
                                     A0 | (A0 >> 1) | (A1 << 31),
                                     A1 | (A1 >> 1) | (A2 << 31));
            else
                drow[1] = make_uint4(A2 | (A2 >> 1) | (A3 << 31),
                                     A3 | (A3 >> 1), 0u, 0u);
        }
    }
}

__device__ __forceinline__ int wpopc(unsigned x) {   // sum of indices of set bits
    return __popc(x & 0xAAAAAAAAu) + 2 * __popc(x & 0xCCCCCCCCu)
         + 4 * __popc(x & 0xF0F0F0F0u) + 8 * __popc(x & 0xFF00FF00u)
         + 16 * __popc(x & 0xFFFF0000u);
}
__device__ __forceinline__ int wpopc64(unsigned long long x) {
    const unsigned lo = (unsigned)x, hi = (unsigned)(x >> 32);
    return wpopc(lo) + wpopc(hi) + 32 * __popc(hi);
}

// ---------------- render: 512 blocks x 256 threads ----------------
// blockIdx&127 -> jcol ; blockIdx>>7 -> i-tile (32 rows) ; lane -> pixel i
// warp w: gathers samples [8w,8w+8); builds table segment w; evals hiddens [8w,8w+8)
__global__ __launch_bounds__(BT) void render_kernel(const float* __restrict__ T4,
                                                    const float* __restrict__ W1,
                                                    const float* __restrict__ b1,
                                                    const float* __restrict__ W2p,
                                                    const float* __restrict__ b2p,
                                                    float* __restrict__ out) {
    __shared__ float4 sE[HIDDEN];            // A, delta, w2, -1/delta
    __shared__ float4 sBC[HIDDEN];           // B, C, D, b1 (fallback)
    __shared__ float2 sVO[HIDDEN];           // (u0 base, row-offset int) per jh
    __shared__ unsigned sMB[BT];             // per-warp 8-bit sample masks
    __shared__ float2 sTab[130 * 32];        // rows 0..64 suffix, 65..129 prefix
    __shared__ float  red[8][32];

    const int t = threadIdx.x;
    const int lane = t & 31;
    const int w = t >> 5;
    const int jcol = blockIdx.x & 127;
    const int i = ((blockIdx.x >> 7) << 5) + lane;
    const float px = (float)i - 63.5f;
    const float py = (float)jcol - 63.5f;

    // ---- prelude ----
    if (t < HIDDEN) {
        float w0 = W1[t], w1 = W1[HIDDEN + t], w2 = W1[2 * HIDDEN + t];
        float A = w0 * T4[0] + w1 * T4[4] + w2 * T4[8];
        float B = w0 * T4[1] + w1 * T4[5] + w2 * T4[9];
        float C = w0 * T4[2] + w1 * T4[6] + w2 * T4[10];
        float D = w0 * T4[3] + w1 * T4[7] + w2 * T4[11];
        float dl = C * 2.0f;  // DZ
        sE[t]  = make_float4(A, dl, W2p[t], -1.0f / dl);
        sBC[t] = make_float4(B, C, D, b1[t]);
        // single window: pz0 = (0 - 31.5) * 2 = -63
        const int off = signbit(dl) ? 65 : 0;   // prefix rows start at 65
        sVO[t] = make_float2(fmaf(py, B, fmaf(-63.0f, C, D + b1[t])),
                             __int_as_float(off));
    }

    const float t00 = __ldg(T4 + 0), t01 = __ldg(T4 + 1), t02 = __ldg(T4 + 2), t03 = __ldg(T4 + 3);
    const float t10 = __ldg(T4 + 4), t11 = __ldg(T4 + 5), t12 = __ldg(T4 + 6), t13 = __ldg(T4 + 7);
    const float t20 = __ldg(T4 + 8), t21 = __ldg(T4 + 9), t22 = __ldg(T4 + 10), t23 = __ldg(T4 + 11);
    const float t30 = __ldg(T4 + 12), t31 = __ldg(T4 + 13), t32 = __ldg(T4 + 14), t33 = __ldg(T4 + 15);
    const bool rigid = (t30 == 0.0f) && (t31 == 0.0f) && (t32 == 0.0f) && (t33 == 1.0f);

    const float cx = fmaf(py, t01, fmaf(px, t00, t03));
    const float cy = fmaf(py, t11, fmaf(px, t10, t13));
    const float cz = fmaf(py, t21, fmaf(px, t20, t23));
    const float cw = fmaf(py, t31, fmaf(px, t30, t33));
    const float cxp = cx + 127.5f;
    const float cyp = cy + 127.5f;
    const float czp = cz + 127.5f;

    // ---- mask phase: 8 samples per warp ----
    const float MAGIC = 12582912.0f;  // 1.5 * 2^23
    unsigned mb = 0, sus = 0;
    float pz = ((float)(w * SPW) - 31.5f) * 2.0f;
    #pragma unroll
    for (int m = 0; m < SPW; m++) {
        const float qx = fmaf(pz, t02, cxp);
        const float qy = fmaf(pz, t12, cyp);
        const float qz = fmaf(pz, t22, czp);
        const int xi = __float2int_rd(qx);
        const int yi = __float2int_rd(qy);
        const int zi = __float2int_rd(qz);
        const float dx = qx - __fsub_rn(__fadd_rn(qx, MAGIC), MAGIC);
        const float dy = qy - __fsub_rn(__fadd_rn(qy, MAGIC), MAGIC);
        const float dz = qz - __fsub_rn(__fadd_rn(qz, MAGIC), MAGIC);
        const float dmin = fminf(fminf(fabsf(dx), fabsf(dy)), fabsf(dz));
        if (dmin < BEPS) sus |= 1u << m;

        unsigned bit = 0;
        if (!(((unsigned)(xi | yi | zi)) & ~255u)) {
            const unsigned widx = ((unsigned)zi << 11) | ((unsigned)yi << 3)
                                | ((unsigned)xi >> 5);
            bit = (__ldg(&g_tab[widx]) >> (xi & 31)) & 1u;
        }
        mb |= bit << m;
        pz += 2.0f;
    }

    // ---- exact fixup of suspect samples (rare) ----
    if (__any_sync(0xffffffffu, sus != 0u)) {
        while (sus) {
            const int m = __ffs(sus) - 1;
            sus &= sus - 1;
            const float pzm = ((float)(w * SPW + m) - 31.5f) * 2.0f;
            const float qx = fmaf(pzm, t02, cx);
            const float qy = fmaf(pzm, t12, cy);
            const float qz = fmaf(pzm, t22, cz);
            const float xn = __fdiv_rn(qx, 63.5f), yn = __fdiv_rn(qy, 63.5f), zn = __fdiv_rn(qz, 63.5f);
            const float xg = __fmul_rn(__fmul_rn(__fadd_rn(xn, 1.0f), 0.5f), 127.0f);
            const float yg = __fmul_rn(__fmul_rn(__fadd_rn(yn, 1.0f), 0.5f), 127.0f);
            const float zg = __fmul_rn(__fmul_rn(__fadd_rn(zn, 1.0f), 0.5f), 127.0f);
            const float xf = floorf(xg), yf = floorf(yg), zf = floorf(zg);
            const int x0 = (int)xf, y0 = (int)yf, z0 = (int)zf;
            const bool bx = xg > xf, by_ = yg > yf, bz_ = zg > zf;
            bool found = false;
            #pragma unroll
            for (int dz_ = 0; dz_ < 2; dz_++) {
                #pragma unroll
                for (int dy_ = 0; dy_ < 2; dy_++) {
                    #pragma unroll
                    for (int dx_ = 0; dx_ < 2; dx_++) {
                        const int zc = z0 + dz_, yc = y0 + dy_, xc = x0 + dx_;
                        const bool inc = (dx_ == 0 || bx) && (dy_ == 0 || by_) && (dz_ == 0 || bz_);
                        const bool val = ((unsigned)xc < 128u) && ((unsigned)yc < 128u)
                                       && ((unsigned)zc < 128u);
                        if (inc && val)
                            found |= ((g_mask[(((zc << 7) + yc) << 2) + (xc >> 5)]
                                       >> (xc & 31)) & 1u) != 0u;
                    }
                }
            }
            mb = (mb & ~(1u << m)) | (((unsigned)found) << m);
        }
    }

    sMB[t] = mb;
    __syncthreads();

    const float b2v = __ldg(b2p);
    float part = 0.0f;

    if (rigid) {
        // ---- cooperative table build: warp w = segment w, lane = pixel ----
        {
            const int pxl = lane, seg = w;
            unsigned long long mb64 = 0ull;
            #pragma unroll
            for (int j = 0; j < 8; j++)
                mb64 |= (unsigned long long)sMB[(j << 5) + pxl] << (8 * j);

            const int s_hi = 8 * seg + 8;
            const unsigned long long tail = (seg == 7) ? 0ull : (mb64 >> s_hi);
            int C0 = __popcll(tail);
            int C1 = s_hi * C0 + wpopc64(tail);
            const float t0f = (float)__popcll(mb64);
            const float t1f = (float)wpopc64(mb64);
            #pragma unroll
            for (int s = 7; s >= 0; --s) {
                const int sr = 8 * seg + s;
                if ((mb64 >> sr) & 1ull) { C0++; C1 += sr; }
                const float c0f = (float)C0, c1f = (float)C1;
                sTab[sr * 32 + pxl] = make_float2(c0f, c1f);                       // suffix
                sTab[(65 + sr) * 32 + pxl] = make_float2(t0f - c0f, t1f - c1f);    // prefix
            }
            if (seg == 7) {
                sTab[64 * 32 + pxl] = make_float2(0.0f, 0.0f);
                sTab[129 * 32 + pxl] = make_float2(t0f, t1f);
            }
        }
        __syncthreads();

        // ---- analytic MLP: 8 hiddens per thread ----
        const float tot0 = sTab[lane].x;     // suffix row 0 = total count
        const unsigned act = __ballot_sync(0xffffffffu, tot0 != 0.0f);
        if (act) {
            const int jh0 = w << 3;
            float acc0 = 0.0f, acc1 = 0.0f;
            #pragma unroll
            for (int jh = jh0; jh < jh0 + 8; jh += 2) {
                {
                    const float4 e = sE[jh];
                    const float2 vo = sVO[jh];
                    const float u0 = fmaf(px, e.x, vo.x);
                    const float g = fminf(fmaxf(u0 * e.w, 0.0f), 64.0f);
                    const int tt = __float2int_ru(g);
                    const float2 s = sTab[(tt + __float_as_int(vo.y)) * 32 + lane];
                    acc0 = fmaf(e.z, fmaf(e.y, s.y, u0 * s.x), acc0);
                }
                {
                    const float4 e = sE[jh + 1];
                    const float2 vo = sVO[jh + 1];
                    const float u0 = fmaf(px, e.x, vo.x);
                    const float g = fminf(fmaxf(u0 * e.w, 0.0f), 64.0f);
                    const int tt = __float2int_ru(g);
                    const float2 s = sTab[(tt + __float_as_int(vo.y)) * 32 + lane];
                    acc1 = fmaf(e.z, fmaf(e.y, s.y, u0 * s.x), acc1);
                }
            }
            part = acc0 + acc1;
            if (w == 0) part = fmaf(b2v, tot0, part);
        }
    } else {
        __syncthreads();   // keep barrier count uniform
        // general path (homogeneous divide): per-warp exact eval of its 8 samples
        float pot = 0.0f;
        for (int m = 0; m < SPW; m++) {
            if ((mb >> m) & 1u) {
                float pzm = ((float)(w * SPW + m) - 31.5f) * 2.0f;
                float qw = fmaf(pzm, t32, cw);
                float rcp = __fdiv_rn(1.0f, qw);
                float s = 0.0f;
                for (int jh = 0; jh < HIDDEN; jh++) {
                    float4 e = sE[jh];
                    float4 bc = sBC[jh];
                    float u = fmaf(px, e.x, fmaf(py, bc.x, fmaf(pzm, bc.y, bc.z)));
                    float a = fmaf(u, rcp, bc.w);
                    s = fmaf(fmaxf(a, 0.0f), e.z, s);
                }
                pot += s + b2v;
            }
        }
        part = pot;
    }

    red[w][lane] = part;
    __syncthreads();
    if (t < 32) {
        float s = 0.0f;
        #pragma unroll
        for (int ww = 0; ww < 8; ww++) s += red[ww][lane];
        out[i * 128 + jcol] = s * 2.0f;  // * DZ
    }
}

// ---------------- launch ----------------
extern "C" void kernel_launch(void* const* d_in, const int* in_sizes, int n_in,
                              void* d_out, int out_size) {
    const float* T  = (const float*)d_in[0];
    const float* V  = (const float*)d_in[1];
    const float* W1 = (const float*)d_in[2];
    const float* b1 = (const float*)d_in[3];
    const float* W2 = (const float*)d_in[4];
    const float* b2 = (const float*)d_in[5];
    float* out = (float*)d_out;

    pack_dilate_kernel<<<289, 352>>>(V);
    render_kernel<<<4 * 128, BT>>>(T, W1, b1, W2, b2, out);
}

// round 13
// speedup vs baseline: 1.0022x; 1.0022x over previous
#include <cuda_runtime.h>
#include <cuda_bf16.h>
#include <cstdint>

#define HIDDEN 64
#define BT 256          // 8 warps
#define SPW 8           // samples gathered per warp (8 warps x 8 = 64)
#define BEPS 2e-4f

// padded OR-dilated table: row (zi,yi) = (z0+64,y0+64), 8 words; bit = x0+64.
__device__ unsigned g_tab[65536 * 8];
__device__ unsigned g_mask[65536];      // base packed mask (exact fixup)

// ---------------- pack + dilate (289 blocks, 17x17 halo tiles) ----------------
__global__ __launch_bounds__(352) void pack_dilate_kernel(const float* __restrict__ vol) {
    __shared__ unsigned sp[81 * 4];   // 9x9 halo packed rows

    const int blk = blockIdx.x;
    const int a = blk / 17, b = blk % 17;
    const int t = threadIdx.x;

    if (t < 324) {
        const int w = t & 3, r = t >> 2;
        const int lz = r / 9, ly = r % 9;
        const int vz = 8 * a - 1 + lz, vy = 8 * b - 1 + ly;
        unsigned acc = 0u;
        if ((unsigned)vz < 128u && (unsigned)vy < 128u) {
            const float4* src = (const float4*)(vol + (((vz << 7) + vy) << 7)) + (w << 3);
            #pragma unroll
            for (int q = 0; q < 8; q++) {
                float4 v = __ldg(&src[q]);
                acc |= ((unsigned)(v.x != 0.0f)
                      | ((unsigned)(v.y != 0.0f) << 1)
                      | ((unsigned)(v.z != 0.0f) << 2)
                      | ((unsigned)(v.w != 0.0f) << 3)) << (q * 4);
            }
        }
        sp[t] = acc;
    }
    __syncthreads();

    if (t < 256 && a < 16 && b < 16) {
        const int r = t >> 2, w = t & 3;
        const int lz = (r >> 3) + 1, ly = (r & 7) + 1;
        const int vz = 8 * a + (r >> 3), vy = 8 * b + (r & 7);
        g_mask[(((vz << 7) + vy) << 2) + w] = sp[(lz * 9 + ly) * 4 + w];
    }

    if (t < 128) {
        const int r = t >> 1, half = t & 1;
        const int lz = r >> 3, ly = r & 7;
        const int z0 = 8 * a - 1 + lz, y0 = 8 * b - 1 + ly;
        if (z0 <= 127 && y0 <= 127) {
            const unsigned* p00 = sp + (lz * 9 + ly) * 4;
            const unsigned A0 = p00[0] | p00[4] | p00[36] | p00[40];
            const unsigned A1 = p00[1] | p00[5] | p00[37] | p00[41];
            const unsigned A2 = p00[2] | p00[6] | p00[38] | p00[42];
            const unsigned A3 = p00[3] | p00[7] | p00[39] | p00[43];
            const unsigned zi = (unsigned)(z0 + 64), yi = (unsigned)(y0 + 64);
            uint4* drow = ((uint4*)g_tab) + (((zi << 8) | yi) << 1);
            if (half == 0)
                drow[0] = make_uint4(0u, A0 << 31,
                                     A0 | (A0 >> 1) | (A1 << 31),
                                     A1 | (A1 >> 1) | (A2 << 31));
            else
                drow[1] = make_uint4(A2 | (A2 >> 1) | (A3 << 31),
                                     A3 | (A3 >> 1), 0u, 0u);
        }
    }

    // PDL: this CTA's output is committed; let dependent grid proceed sooner.
    asm volatile("griddepcontrol.launch_dependents;");
}

__device__ __forceinline__ int wpopc(unsigned x) {   // sum of indices of set bits
    return __popc(x & 0xAAAAAAAAu) + 2 * __popc(x & 0xCCCCCCCCu)
         + 4 * __popc(x & 0xF0F0F0F0u) + 8 * __popc(x & 0xFF00FF00u)
         + 16 * __popc(x & 0xFFFF0000u);
}
__device__ __forceinline__ int wpopc64(unsigned long long x) {
    const unsigned lo = (unsigned)x, hi = (unsigned)(x >> 32);
    return wpopc(lo) + wpopc(hi) + 32 * __popc(hi);
}

// ---------------- render: 512 blocks x 256 threads (PDL secondary) ----------
// blockIdx&127 -> jcol ; blockIdx>>7 -> i-tile (32 rows) ; lane -> pixel i
// warp w: gathers samples [8w,8w+8); builds table segment w; evals hiddens [8w,8w+8)
__global__ __launch_bounds__(BT) void render_kernel(const float* __restrict__ T4,
                                                    const float* __restrict__ W1,
                                                    const float* __restrict__ b1,
                                                    const float* __restrict__ W2p,
                                                    const float* __restrict__ b2p,
                                                    float* __restrict__ out) {
    __shared__ float4 sE[HIDDEN];            // A, delta, w2, -1/delta
    __shared__ float4 sBC[HIDDEN];           // B, C, D, b1 (fallback)
    __shared__ float2 sVO[HIDDEN];           // (u0 base, row-offset int) per jh
    __shared__ unsigned sMB[BT];             // per-warp 8-bit sample masks
    __shared__ float2 sTab[130 * 32];        // rows 0..64 suffix, 65..129 prefix
    __shared__ float  red[8][32];

    const int t = threadIdx.x;
    const int lane = t & 31;
    const int w = t >> 5;
    const int jcol = blockIdx.x & 127;
    const int i = ((blockIdx.x >> 7) << 5) + lane;
    const float px = (float)i - 63.5f;
    const float py = (float)jcol - 63.5f;

    // ---- prelude (overlaps pack kernel via PDL; touches only W1/T4/b1/W2) ----
    if (t < HIDDEN) {
        float w0 = W1[t], w1 = W1[HIDDEN + t], w2 = W1[2 * HIDDEN + t];
        float A = w0 * T4[0] + w1 * T4[4] + w2 * T4[8];
        float B = w0 * T4[1] + w1 * T4[5] + w2 * T4[9];
        float C = w0 * T4[2] + w1 * T4[6] + w2 * T4[10];
        float D = w0 * T4[3] + w1 * T4[7] + w2 * T4[11];
        float dl = C * 2.0f;  // DZ
        sE[t]  = make_float4(A, dl, W2p[t], -1.0f / dl);
        sBC[t] = make_float4(B, C, D, b1[t]);
        // single window: pz0 = (0 - 31.5) * 2 = -63
        const int off = signbit(dl) ? 65 : 0;   // prefix rows start at 65
        sVO[t] = make_float2(fmaf(py, B, fmaf(-63.0f, C, D + b1[t])),
                             __int_as_float(off));
    }

    const float t00 = __ldg(T4 + 0), t01 = __ldg(T4 + 1), t02 = __ldg(T4 + 2), t03 = __ldg(T4 + 3);
    const float t10 = __ldg(T4 + 4), t11 = __ldg(T4 + 5), t12 = __ldg(T4 + 6), t13 = __ldg(T4 + 7);
    const float t20 = __ldg(T4 + 8), t21 = __ldg(T4 + 9), t22 = __ldg(T4 + 10), t23 = __ldg(T4 + 11);
    const float t30 = __ldg(T4 + 12), t31 = __ldg(T4 + 13), t32 = __ldg(T4 + 14), t33 = __ldg(T4 + 15);
    const bool rigid = (t30 == 0.0f) && (t31 == 0.0f) && (t32 == 0.0f) && (t33 == 1.0f);

    const float cx = fmaf(py, t01, fmaf(px, t00, t03));
    const float cy = fmaf(py, t11, fmaf(px, t10, t13));
    const float cz = fmaf(py, t21, fmaf(px, t20, t23));
    const float cw = fmaf(py, t31, fmaf(px, t30, t33));
    const float cxp = cx + 127.5f;
    const float cyp = cy + 127.5f;
    const float czp = cz + 127.5f;

    // ---- PDL: wait for pack_dilate's g_tab/g_mask to be visible ----
    asm volatile("griddepcontrol.wait;" ::: "memory");

    // ---- mask phase: 8 samples per warp ----
    const float MAGIC = 12582912.0f;  // 1.5 * 2^23
    unsigned mb = 0, sus = 0;
    float pz = ((float)(w * SPW) - 31.5f) * 2.0f;
    #pragma unroll
    for (int m = 0; m < SPW; m++) {
        const float qx = fmaf(pz, t02, cxp);
        const float qy = fmaf(pz, t12, cyp);
        const float qz = fmaf(pz, t22, czp);
        const int xi = __float2int_rd(qx);
        const int yi = __float2int_rd(qy);
        const int zi = __float2int_rd(qz);
        const float dx = qx - __fsub_rn(__fadd_rn(qx, MAGIC), MAGIC);
        const float dy = qy - __fsub_rn(__fadd_rn(qy, MAGIC), MAGIC);
        const float dz = qz - __fsub_rn(__fadd_rn(qz, MAGIC), MAGIC);
        const float dmin = fminf(fminf(fabsf(dx), fabsf(dy)), fabsf(dz));
        if (dmin < BEPS) sus |= 1u << m;

        unsigned bit = 0;
        if (!(((unsigned)(xi | yi | zi)) & ~255u)) {
            const unsigned widx = ((unsigned)zi << 11) | ((unsigned)yi << 3)
                                | ((unsigned)xi >> 5);
            bit = (__ldg(&g_tab[widx]) >> (xi & 31)) & 1u;
        }
        mb |= bit << m;
        pz += 2.0f;
    }

    // ---- exact fixup of suspect samples (rare) ----
    if (__any_sync(0xffffffffu, sus != 0u)) {
        while (sus) {
            const int m = __ffs(sus) - 1;
            sus &= sus - 1;
            const float pzm = ((float)(w * SPW + m) - 31.5f) * 2.0f;
            const float qx = fmaf(pzm, t02, cx);
            const float qy = fmaf(pzm, t12, cy);
            const float qz = fmaf(pzm, t22, cz);
            const float xn = __fdiv_rn(qx, 63.5f), yn = __fdiv_rn(qy, 63.5f), zn = __fdiv_rn(qz, 63.5f);
            const float xg = __fmul_rn(__fmul_rn(__fadd_rn(xn, 1.0f), 0.5f), 127.0f);
            const float yg = __fmul_rn(__fmul_rn(__fadd_rn(yn, 1.0f), 0.5f), 127.0f);
            const float zg = __fmul_rn(__fmul_rn(__fadd_rn(zn, 1.0f), 0.5f), 127.0f);
            const float xf = floorf(xg), yf = floorf(yg), zf = floorf(zg);
            const int x0 = (int)xf, y0 = (int)yf, z0 = (int)zf;
            const bool bx = xg > xf, by_ = yg > yf, bz_ = zg > zf;
            bool found = false;
            #pragma unroll
            for (int dz_ = 0; dz_ < 2; dz_++) {
                #pragma unroll
                for (int dy_ = 0; dy_ < 2; dy_++) {
                    #pragma unroll
                    for (int dx_ = 0; dx_ < 2; dx_++) {
                        const int zc = z0 + dz_, yc = y0 + dy_, xc = x0 + dx_;
                        const bool inc = (dx_ == 0 || bx) && (dy_ == 0 || by_) && (dz_ == 0 || bz_);
                        const bool val = ((unsigned)xc < 128u) && ((unsigned)yc < 128u)
                                       && ((unsigned)zc < 128u);
                        if (inc && val)
                            found |= ((g_mask[(((zc << 7) + yc) << 2) + (xc >> 5)]
                                       >> (xc & 31)) & 1u) != 0u;
                    }
                }
            }
            mb = (mb & ~(1u << m)) | (((unsigned)found) << m);
        }
    }

    sMB[t] = mb;
    __syncthreads();

    const float b2v = __ldg(b2p);
    float part = 0.0f;

    if (rigid) {
        // ---- cooperative table build: warp w = segment w, lane = pixel ----
        {
            const int pxl = lane, seg = w;
            unsigned long long mb64 = 0ull;
            #pragma unroll
            for (int j = 0; j < 8; j++)
                mb64 |= (unsigned long long)sMB[(j << 5) + pxl] << (8 * j);

            const int s_hi = 8 * seg + 8;
            const unsigned long long tail = (seg == 7) ? 0ull : (mb64 >> s_hi);
            int C0 = __popcll(tail);
            int C1 = s_hi * C0 + wpopc64(tail);
            const float t0f = (float)__popcll(mb64);
            const float t1f = (float)wpopc64(mb64);
            #pragma unroll
            for (int s = 7; s >= 0; --s) {
                const int sr = 8 * seg + s;
                if ((mb64 >> sr) & 1ull) { C0++; C1 += sr; }
                const float c0f = (float)C0, c1f = (float)C1;
                sTab[sr * 32 + pxl] = make_float2(c0f, c1f);                       // suffix
                sTab[(65 + sr) * 32 + pxl] = make_float2(t0f - c0f, t1f - c1f);    // prefix
            }
            if (seg == 7) {
                sTab[64 * 32 + pxl] = make_float2(0.0f, 0.0f);
                sTab[129 * 32 + pxl] = make_float2(t0f, t1f);
            }
        }
        __syncthreads();

        // ---- analytic MLP: 8 hiddens per thread ----
        const float tot0 = sTab[lane].x;     // suffix row 0 = total count
        const unsigned act = __ballot_sync(0xffffffffu, tot0 != 0.0f);
        if (act) {
            const int jh0 = w << 3;
            float acc0 = 0.0f, acc1 = 0.0f;
            #pragma unroll
            for (int jh = jh0; jh < jh0 + 8; jh += 2) {
                {
                    const float4 e = sE[jh];
                    const float2 vo = sVO[jh];
                    const float u0 = fmaf(px, e.x, vo.x);
                    const float g = fminf(fmaxf(u0 * e.w, 0.0f), 64.0f);
                    const int tt = __float2int_ru(g);
                    const float2 s = sTab[(tt + __float_as_int(vo.y)) * 32 + lane];
                    acc0 = fmaf(e.z, fmaf(e.y, s.y, u0 * s.x), acc0);
                }
                {
                    const float4 e = sE[jh + 1];
                    const float2 vo = sVO[jh + 1];
                    const float u0 = fmaf(px, e.x, vo.x);
                    const float g = fminf(fmaxf(u0 * e.w, 0.0f), 64.0f);
                    const int tt = __float2int_ru(g);
                    const float2 s = sTab[(tt + __float_as_int(vo.y)) * 32 + lane];
                    acc1 = fmaf(e.z, fmaf(e.y, s.y, u0 * s.x), acc1);
                }
            }
            part = acc0 + acc1;
            if (w == 0) part = fmaf(b2v, tot0, part);
        }
    } else {
        __syncthreads();   // keep barrier count uniform
        // general path (homogeneous divide): per-warp exact eval of its 8 samples
        float pot = 0.0f;
        for (int m = 0; m < SPW; m++) {
            if ((mb >> m) & 1u) {
                float pzm = ((float)(w * SPW + m) - 31.5f) * 2.0f;
                float qw = fmaf(pzm, t32, cw);
                float rcp = __fdiv_rn(1.0f, qw);
                float s = 0.0f;
                for (int jh = 0; jh < HIDDEN; jh++) {
                    float4 e = sE[jh];
                    float4 bc = sBC[jh];
                    float u = fmaf(px, e.x, fmaf(py, bc.x, fmaf(pzm, bc.y, bc.z)));
                    float a = fmaf(u, rcp, bc.w);
                    s = fmaf(fmaxf(a, 0.0f), e.z, s);
                }
                pot += s + b2v;
            }
        }
        part = pot;
    }

    red[w][lane] = part;
    __syncthreads();
    if (t < 32) {
        float s = 0.0f;
        #pragma unroll
        for (int ww = 0; ww < 8; ww++) s += red[ww][lane];
        out[i * 128 + jcol] = s * 2.0f;  // * DZ
    }
}

// ---------------- launch ----------------
extern "C" void kernel_launch(void* const* d_in, const int* in_sizes, int n_in,
                              void* d_out, int out_size) {
    const float* T  = (const float*)d_in[0];
    const float* V  = (const float*)d_in[1];
    const float* W1 = (const float*)d_in[2];
    const float* b1 = (const float*)d_in[3];
    const float* W2 = (const float*)d_in[4];
    const float* b2 = (const float*)d_in[5];
    float* out = (float*)d_out;

    pack_dilate_kernel<<<289, 352>>>(V);

    // PDL launch: render may start (prelude) while pack is still running.
    cudaLaunchConfig_t cfg = {};
    cfg.gridDim = dim3(4 * 128);
    cfg.blockDim = dim3(BT);
    cfg.dynamicSmemBytes = 0;
    cfg.stream = 0;
    cudaLaunchAttribute attrs[1];
    attrs[0].id = cudaLaunchAttributeProgrammaticStreamSerialization;
    attrs[0].val.programmaticStreamSerializationAllowed = 1;
    cfg.attrs = attrs;
    cfg.numAttrs = 1;
    cudaLaunchKernelEx(&cfg, render_kernel, T, W1, b1, W2, b2, out);
}